// round 5
// baseline (speedup 1.0000x reference)
#include <cuda_runtime.h>
#include <math.h>

#define SUB_NO 20
#define T_NO 201
#define E_NO 2000
#define I_NO 500
#define T_DATA 20000

// Output layout: concat of (V[20000], out_filters[40*201], C_syn_e[20*2000], C_syn_i[20*500])
#define OFF_V  0
#define OFF_F  (T_DATA)                   // 20000
#define OFF_CE (OFF_F + 40 * T_NO)        // 28040
#define OFF_CI (OFF_CE + SUB_NO * E_NO)   // 68040

// ---------------- scratch ----------------
__device__ float g_CTe[E_NO * SUB_NO];
__device__ float g_CTi[I_NO * SUB_NO];
__device__ float g_syne[T_DATA * SUB_NO];
__device__ float g_syni[T_DATA * SUB_NO];
__device__ float g_f0[T_DATA * SUB_NO];   // filtered E
__device__ float g_f1[T_DATA * SUB_NO];   // filtered I

// compact spike indices (scan kernel output)
#define ECAP 288   // ushort idx capacity per row (mean 100, sigma 9.7 -> 19 sigma)
#define ICAP 96    // mean 25, sigma 4.9 -> 14 sigma
__device__ ushort g_eidx[(size_t)T_DATA * ECAP];
__device__ ushort g_iidx[(size_t)T_DATA * ICAP];
__device__ int    g_enk[T_DATA];          // number of uint4 index groups (8 idx each)
__device__ int    g_ink[T_DATA];

// param pack
#define P_GAIN  0
#define P_THETA 32
#define P_RE    64
#define P_BE    96
#define P_BDE   128
#define P_C1E   160
#define P_RI    192
#define P_BI    224
#define P_BDI   256
#define P_C1I   288
#define P_VO    320
__device__ float g_par[336];

// ---------------- K1: softmax + filters + IIR params ----------------
__global__ void prep_kernel(const float* __restrict__ Craw_e,
                            const float* __restrict__ Craw_i,
                            const float* __restrict__ Wsyn,
                            const float* __restrict__ Tausyn,
                            const float* __restrict__ Dsyn,
                            const float* __restrict__ Wsub,
                            const float* __restrict__ Vo,
                            const float* __restrict__ Theta,
                            float* __restrict__ out)
{
    int tid = blockIdx.x * blockDim.x + threadIdx.x;

    if (tid < E_NO + I_NO) {
        const float* raw;
        float* o;
        float* ct;
        int stride, e;
        if (tid < E_NO) { raw = Craw_e; o = out + OFF_CE; ct = g_CTe; stride = E_NO; e = tid; }
        else            { raw = Craw_i; o = out + OFF_CI; ct = g_CTi; stride = I_NO; e = tid - E_NO; }
        float v[SUB_NO];
        float m = -1e30f;
#pragma unroll
        for (int j = 0; j < SUB_NO; ++j) { v[j] = raw[j * stride + e]; m = fmaxf(m, v[j]); }
        float s = 0.f;
#pragma unroll
        for (int j = 0; j < SUB_NO; ++j) { v[j] = expf(v[j] - m); s += v[j]; }
        float inv = 1.f / s;
#pragma unroll
        for (int j = 0; j < SUB_NO; ++j) {
            float w = v[j] * inv;
            o[j * stride + e]  = w;
            ct[e * SUB_NO + j] = w;
        }
    }

    int f = tid - (E_NO + I_NO);
    if (f >= 0 && f < 40 * T_NO) {
        int row  = f / T_NO;
        int k    = f - row * T_NO;
        int type = row / SUB_NO;
        int s    = row - type * SUB_NO;
        float delta = expf(Dsyn[s * 2 + type]);
        float tau   = expf(Tausyn[s * 2 + type]);
        float w     = expf(Wsyn[s * 2 + type]);
        float tt    = fmaxf((float)k - delta, 0.f) / tau;
        float val   = tt * expf(-tt) * w;
        if (type) val = -val;
        out[OFF_F + row * T_NO + k] = val;
    }

    int p = tid - (E_NO + I_NO + 40 * T_NO);
    if (p >= 0 && p < SUB_NO) {
        g_par[P_GAIN  + p] = expf(Wsub[p]);
        g_par[P_THETA + p] = Theta[p];
#pragma unroll
        for (int type = 0; type < 2; ++type) {
            float delta = expf(Dsyn[p * 2 + type]);
            float tau   = expf(Tausyn[p * 2 + type]);
            float w     = expf(Wsyn[p * 2 + type]);
            float r     = expf(-1.f / tau);
            float B     = w * expf(delta / tau) / tau;
            if (type) B = -B;
            float c1 = (delta > 1.f) ? B * (delta - 1.f) * r : 0.f;
            g_par[(type ? P_RI  : P_RE ) + p] = r;
            g_par[(type ? P_BI  : P_BE ) + p] = B;
            g_par[(type ? P_BDI : P_BDE) + p] = B * delta;
            g_par[(type ? P_C1I : P_C1E) + p] = c1;
        }
    }
    if (tid == E_NO + I_NO + 40 * T_NO + SUB_NO) g_par[P_VO] = Vo[0];
}

// ---------------- K-A: streaming scan/compaction (pure bandwidth) ----------------
// NFULL full 32-lane float4 iters + one tail iter (TAIL lanes). PF-deep LDG ring.
template<int NFULL, int TAIL, int PF>
__device__ __forceinline__ void row_scan(const float4* __restrict__ Sv, int npad,
                                         ushort* __restrict__ outIdx, int* __restrict__ outNk,
                                         int lane, unsigned lt)
{
    constexpr int NT = NFULL + 1;
    const float4 z4 = make_float4(0.f, 0.f, 0.f, 0.f);
    float4 ring[PF];
#pragma unroll
    for (int p = 0; p < PF; ++p) {
        if (p < NT) ring[p] = (p < NFULL || lane < TAIL) ? Sv[p * 32 + lane] : z4;
        else        ring[p] = z4;
    }
    int cnt = 0;
#pragma unroll
    for (int it = 0; it < NT; ++it) {
        float4 v = ring[it % PF];
        if (it + PF < NT)
            ring[it % PF] = ((it + PF) < NFULL || lane < TAIL) ? Sv[(it + PF) * 32 + lane] : z4;
        unsigned m0 = __ballot_sync(0xffffffffu, v.x != 0.f);
        unsigned m1 = __ballot_sync(0xffffffffu, v.y != 0.f);
        unsigned m2 = __ballot_sync(0xffffffffu, v.z != 0.f);
        unsigned m3 = __ballot_sync(0xffffffffu, v.w != 0.f);
        int t0 = __popc(m0), t1 = __popc(m1), t2 = __popc(m2), t3 = __popc(m3);
        int p0 = cnt + __popc(m0 & lt);
        int p1 = cnt + t0 + __popc(m1 & lt);
        int p2 = cnt + t0 + t1 + __popc(m2 & lt);
        int p3 = cnt + t0 + t1 + t2 + __popc(m3 & lt);
        int base = (it * 32 + lane) * 4;
        if (v.x != 0.f) outIdx[p0] = (ushort)(base);
        if (v.y != 0.f) outIdx[p1] = (ushort)(base + 1);
        if (v.z != 0.f) outIdx[p2] = (ushort)(base + 2);
        if (v.w != 0.f) outIdx[p3] = (ushort)(base + 3);
        cnt += t0 + t1 + t2 + t3;
    }
    int cpad = (cnt + 7) & ~7;
    if (lane < cpad - cnt) outIdx[cnt + lane] = (ushort)npad;  // dummy -> zeroed table row
    if (lane == 0) *outNk = cpad >> 3;
}

#define KA_THREADS 256
#define KA_WARPS   8

__global__ void __launch_bounds__(KA_THREADS)
scan_kernel(const float* __restrict__ Se, const float* __restrict__ Si)
{
    int warp = threadIdx.x >> 5;
    int lane = threadIdx.x & 31;
    unsigned lt = (1u << lane) - 1u;
    int gwarp = blockIdx.x * KA_WARPS + warp;
    int totw  = gridDim.x * KA_WARPS;

    for (int row = gwarp; row < T_DATA; row += totw) {
        row_scan<15, 20, 6>((const float4*)(Se + (size_t)row * E_NO), E_NO,
                            g_eidx + (size_t)row * ECAP, g_enk + row, lane, lt);
        row_scan<3, 29, 4>((const float4*)(Si + (size_t)row * I_NO), I_NO,
                           g_iidx + (size_t)row * ICAP, g_ink + row, lane, lt);
    }
}

// ---------------- K-B: table gather (issue-bound, smem-resident weights) ----------------
#define KB_THREADS 1024
#define KB_WARPS   32
#define SH_I_OFF   40032   // floats: sh_e 2001x20 rows (+pad to 40032), sh_i 501x20
#define SH_TOTAL_BYTES (50064 * 4)   // 200256

__device__ __forceinline__ float gather_sum(const uint4* __restrict__ ib, int nk,
                                            const float* __restrict__ tab, int jj)
{
    float acc0 = 0.f, acc1 = 0.f;
#pragma unroll 2
    for (int k = 0; k < nk; ++k) {
        uint4 w = ib[k];
        acc0 += tab[(w.x & 0xffffu) * SUB_NO + jj];
        acc1 += tab[(w.x >> 16)     * SUB_NO + jj];
        acc0 += tab[(w.y & 0xffffu) * SUB_NO + jj];
        acc1 += tab[(w.y >> 16)     * SUB_NO + jj];
        acc0 += tab[(w.z & 0xffffu) * SUB_NO + jj];
        acc1 += tab[(w.z >> 16)     * SUB_NO + jj];
        acc0 += tab[(w.w & 0xffffu) * SUB_NO + jj];
        acc1 += tab[(w.w >> 16)     * SUB_NO + jj];
    }
    return acc0 + acc1;
}

__global__ void __launch_bounds__(KB_THREADS, 1)
gather_kernel()
{
    extern __shared__ float sh[];
    float* sh_e = sh;
    float* sh_i = sh + SH_I_OFF;
    {
        const float4* se4 = (const float4*)g_CTe;
        const float4* si4 = (const float4*)g_CTi;
        float4* de = (float4*)sh_e;
        float4* di = (float4*)sh_i;
        for (int i = threadIdx.x; i < (E_NO * SUB_NO) / 4; i += KB_THREADS) de[i] = se4[i];
        for (int i = threadIdx.x; i < (I_NO * SUB_NO) / 4; i += KB_THREADS) di[i] = si4[i];
        if (threadIdx.x < 32) sh_e[E_NO * SUB_NO + threadIdx.x] = 0.f;  // pad row 2000
        if (threadIdx.x < 32) sh_i[I_NO * SUB_NO + threadIdx.x] = 0.f;  // pad row 500
    }
    __syncthreads();

    int warp = threadIdx.x >> 5;
    int lane = threadIdx.x & 31;
    int jj = (lane < SUB_NO) ? lane : 0;
    int gwarp = blockIdx.x * KB_WARPS + warp;
    int totw  = gridDim.x * KB_WARPS;

    for (int row = gwarp; row < T_DATA; row += totw) {
        int enk = g_enk[row];
        int ink = g_ink[row];
        float ae = gather_sum((const uint4*)(g_eidx + (size_t)row * ECAP), enk, sh_e, jj);
        float ai = gather_sum((const uint4*)(g_iidx + (size_t)row * ICAP), ink, sh_i, jj);
        if (lane < SUB_NO) {
            g_syne[row * SUB_NO + lane] = ae;
            g_syni[row * SUB_NO + lane] = ai;
        }
    }
}

// ---------------- K3: chunked 2-state IIR, E and I decoupled ----------------
#define CH   64
#define NCH  ((T_DATA + CH - 1) / CH)   // 313
#define WARM 96                          // r^96 <= 3e-12 rel: far under tolerance

__global__ void iir_kernel()
{
    int tid = blockIdx.x * blockDim.x + threadIdx.x;
    if (tid >= 2 * NCH * SUB_NO) return;
    int type  = (tid >= NCH * SUB_NO);
    int q     = tid - type * NCH * SUB_NO;
    int s     = q % SUB_NO;
    int chunk = q / SUB_NO;
    int t0   = chunk * CH;
    int tend = min(t0 + CH, T_DATA);
    int tw   = max(t0 - WARM, 0);

    const float* __restrict__ x = type ? g_syni : g_syne;
    float*       __restrict__ y = type ? g_f1   : g_f0;
    float r  = g_par[(type ? P_RI  : P_RE ) + s];
    float B  = g_par[(type ? P_BI  : P_BE ) + s];
    float BD = g_par[(type ? P_BDI : P_BDE) + s];
    float C1 = g_par[(type ? P_C1I : P_C1E) + s];

    float s1 = 0.f, s2 = 0.f, xp = 0.f;
    for (int t = tw; t < tend; ++t) {
        float xv = x[t * SUB_NO + s];
        float ns2 = r * (s1 + s2);
        float ns1 = fmaf(r, s1, xv);
        s1 = ns1; s2 = ns2;
        if (t >= t0)
            y[t * SUB_NO + s] = B * s2 - BD * s1 + BD * xv + C1 * xp;
        xp = xv;
    }
}

// ---------------- K4: per-timestep subunit tree + V ----------------
__device__ __forceinline__ float fast_tanh(float x)
{
    x = fminf(fmaxf(x, -15.f), 15.f);
    float e = __expf(2.f * x);
    return __fdividef(e - 1.f, e + 1.f);
}

__global__ void tree_kernel(float* __restrict__ out)
{
    int t = blockIdx.x * blockDim.x + threadIdx.x;
    if (t >= T_DATA) return;

    float syn[SUB_NO];
    const float4* p0 = (const float4*)(g_f0 + t * SUB_NO);
    const float4* p1 = (const float4*)(g_f1 + t * SUB_NO);
#pragma unroll
    for (int q = 0; q < 5; ++q) {
        float4 a = p0[q];
        float4 b = p1[q];
        syn[4 * q]     = a.x + b.x;
        syn[4 * q + 1] = a.y + b.y;
        syn[4 * q + 2] = a.z + b.z;
        syn[4 * q + 3] = a.w + b.w;
    }
    float gain[SUB_NO], th[SUB_NO];
#pragma unroll
    for (int j = 0; j < SUB_NO; ++j) { gain[j] = g_par[P_GAIN + j]; th[j] = g_par[P_THETA + j]; }

    float sub[SUB_NO];
#pragma unroll
    for (int i = SUB_NO - 1; i >= 0; --i) {
        float v = syn[i] + th[i];
        if (2 * i + 1 < SUB_NO) v = fmaf(gain[2 * i + 1], sub[2 * i + 1], v);
        if (2 * i + 2 < SUB_NO) v = fmaf(gain[2 * i + 2], sub[2 * i + 2], v);
        sub[i] = fast_tanh(v);
    }
    out[t] = fmaf(sub[0], gain[0], g_par[P_VO]);
}

// ---------------- launch ----------------
extern "C" void kernel_launch(void* const* d_in, const int* in_sizes, int n_in,
                              void* d_out, int out_size)
{
    const float* Se     = (const float*)d_in[0];
    const float* Si     = (const float*)d_in[1];
    const float* Wsyn   = (const float*)d_in[3];
    const float* Tausyn = (const float*)d_in[4];
    const float* Dsyn   = (const float*)d_in[5];
    const float* Wsub   = (const float*)d_in[6];
    const float* Vo     = (const float*)d_in[7];
    const float* Theta  = (const float*)d_in[8];
    const float* Ce     = (const float*)d_in[9];
    const float* Ci     = (const float*)d_in[10];
    float* out = (float*)d_out;

    int prep_threads = E_NO + I_NO + 40 * T_NO + SUB_NO + 1;  // 10561
    prep_kernel<<<(prep_threads + 255) / 256, 256>>>(Ce, Ci, Wsyn, Tausyn, Dsyn, Wsub, Vo, Theta, out);

    // K-A: pure streaming compaction, high occupancy (no smem)
    scan_kernel<<<1184, KA_THREADS>>>(Se, Si);

    // K-B: smem-table gather
    cudaFuncSetAttribute(gather_kernel, cudaFuncAttributeMaxDynamicSharedMemorySize, SH_TOTAL_BYTES);
    gather_kernel<<<148, KB_THREADS, SH_TOTAL_BYTES>>>();

    iir_kernel<<<(2 * NCH * SUB_NO + 127) / 128, 128>>>();
    tree_kernel<<<(T_DATA + 127) / 128, 128>>>(out);
}

// round 6
// speedup vs baseline: 1.4286x; 1.4286x over previous
#include <cuda_runtime.h>
#include <math.h>

#define SUB_NO 20
#define T_NO 201
#define E_NO 2000
#define I_NO 500
#define T_DATA 20000

// Output layout: concat of (V[20000], out_filters[40*201], C_syn_e[20*2000], C_syn_i[20*500])
#define OFF_V  0
#define OFF_F  (T_DATA)                   // 20000
#define OFF_CE (OFF_F + 40 * T_NO)        // 28040
#define OFF_CI (OFF_CE + SUB_NO * E_NO)   // 68040

#define PAD 96   // IIR warm-up depth: r^96 <= 1e-12 relative, far below 1e-3 tolerance

// ---------------- scratch ----------------
__device__ float g_CTe[E_NO * SUB_NO];
__device__ float g_CTi[I_NO * SUB_NO];
__device__ float g_synZe[(PAD + T_DATA) * SUB_NO];  // zero-padded head, then syn_e
__device__ float g_synZi[(PAD + T_DATA) * SUB_NO];
__device__ float g_f0[T_DATA * SUB_NO];   // filtered E
__device__ float g_f1[T_DATA * SUB_NO];   // filtered I

// compact spike indices (scan kernel output)
#define ECAP 288
#define ICAP 96
__device__ ushort g_eidx[(size_t)T_DATA * ECAP];
__device__ ushort g_iidx[(size_t)T_DATA * ICAP];
__device__ int    g_enk[T_DATA];
__device__ int    g_ink[T_DATA];

// param pack
#define P_GAIN  0
#define P_THETA 32
#define P_RE    64
#define P_BE    96
#define P_BDE   128
#define P_C1E   160
#define P_RI    192
#define P_BI    224
#define P_BDI   256
#define P_C1I   288
#define P_VO    320
__device__ float g_par[336];

// ---------------- K1: softmax + filters + IIR params + pad-zeroing ----------------
__global__ void prep_kernel(const float* __restrict__ Craw_e,
                            const float* __restrict__ Craw_i,
                            const float* __restrict__ Wsyn,
                            const float* __restrict__ Tausyn,
                            const float* __restrict__ Dsyn,
                            const float* __restrict__ Wsub,
                            const float* __restrict__ Vo,
                            const float* __restrict__ Theta,
                            float* __restrict__ out)
{
    int tid = blockIdx.x * blockDim.x + threadIdx.x;

    // zero the IIR warm-up pad rows
    if (tid < PAD * SUB_NO) {
        g_synZe[tid] = 0.f;
        g_synZi[tid] = 0.f;
    }

    if (tid < E_NO + I_NO) {
        const float* raw;
        float* o;
        float* ct;
        int stride, e;
        if (tid < E_NO) { raw = Craw_e; o = out + OFF_CE; ct = g_CTe; stride = E_NO; e = tid; }
        else            { raw = Craw_i; o = out + OFF_CI; ct = g_CTi; stride = I_NO; e = tid - E_NO; }
        float v[SUB_NO];
        float m = -1e30f;
#pragma unroll
        for (int j = 0; j < SUB_NO; ++j) { v[j] = raw[j * stride + e]; m = fmaxf(m, v[j]); }
        float s = 0.f;
#pragma unroll
        for (int j = 0; j < SUB_NO; ++j) { v[j] = expf(v[j] - m); s += v[j]; }
        float inv = 1.f / s;
#pragma unroll
        for (int j = 0; j < SUB_NO; ++j) {
            float w = v[j] * inv;
            o[j * stride + e]  = w;
            ct[e * SUB_NO + j] = w;
        }
    }

    int f = tid - (E_NO + I_NO);
    if (f >= 0 && f < 40 * T_NO) {
        int row  = f / T_NO;
        int k    = f - row * T_NO;
        int type = row / SUB_NO;
        int s    = row - type * SUB_NO;
        float delta = expf(Dsyn[s * 2 + type]);
        float tau   = expf(Tausyn[s * 2 + type]);
        float w     = expf(Wsyn[s * 2 + type]);
        float tt    = fmaxf((float)k - delta, 0.f) / tau;
        float val   = tt * expf(-tt) * w;
        if (type) val = -val;
        out[OFF_F + row * T_NO + k] = val;
    }

    int p = tid - (E_NO + I_NO + 40 * T_NO);
    if (p >= 0 && p < SUB_NO) {
        g_par[P_GAIN  + p] = expf(Wsub[p]);
        g_par[P_THETA + p] = Theta[p];
#pragma unroll
        for (int type = 0; type < 2; ++type) {
            float delta = expf(Dsyn[p * 2 + type]);
            float tau   = expf(Tausyn[p * 2 + type]);
            float w     = expf(Wsyn[p * 2 + type]);
            float r     = expf(-1.f / tau);
            float B     = w * expf(delta / tau) / tau;
            if (type) B = -B;
            float c1 = (delta > 1.f) ? B * (delta - 1.f) * r : 0.f;
            g_par[(type ? P_RI  : P_RE ) + p] = r;
            g_par[(type ? P_BI  : P_BE ) + p] = B;
            g_par[(type ? P_BDI : P_BDE) + p] = B * delta;
            g_par[(type ? P_C1I : P_C1E) + p] = c1;
        }
    }
    if (tid == E_NO + I_NO + 40 * T_NO + SUB_NO) g_par[P_VO] = Vo[0];
}

// ---------------- K-A: streaming scan/compaction (pure bandwidth) ----------------
template<int NFULL, int TAIL, int PF>
__device__ __forceinline__ void row_scan(const float4* __restrict__ Sv, int npad,
                                         ushort* __restrict__ outIdx, int* __restrict__ outNk,
                                         int lane, unsigned lt)
{
    constexpr int NT = NFULL + 1;
    const float4 z4 = make_float4(0.f, 0.f, 0.f, 0.f);
    float4 ring[PF];
#pragma unroll
    for (int p = 0; p < PF; ++p) {
        if (p < NT) ring[p] = (p < NFULL || lane < TAIL) ? Sv[p * 32 + lane] : z4;
        else        ring[p] = z4;
    }
    int cnt = 0;
#pragma unroll
    for (int it = 0; it < NT; ++it) {
        float4 v = ring[it % PF];
        if (it + PF < NT)
            ring[it % PF] = ((it + PF) < NFULL || lane < TAIL) ? Sv[(it + PF) * 32 + lane] : z4;
        unsigned m0 = __ballot_sync(0xffffffffu, v.x != 0.f);
        unsigned m1 = __ballot_sync(0xffffffffu, v.y != 0.f);
        unsigned m2 = __ballot_sync(0xffffffffu, v.z != 0.f);
        unsigned m3 = __ballot_sync(0xffffffffu, v.w != 0.f);
        int t0 = __popc(m0), t1 = __popc(m1), t2 = __popc(m2), t3 = __popc(m3);
        int p0 = cnt + __popc(m0 & lt);
        int p1 = cnt + t0 + __popc(m1 & lt);
        int p2 = cnt + t0 + t1 + __popc(m2 & lt);
        int p3 = cnt + t0 + t1 + t2 + __popc(m3 & lt);
        int base = (it * 32 + lane) * 4;
        if (v.x != 0.f) outIdx[p0] = (ushort)(base);
        if (v.y != 0.f) outIdx[p1] = (ushort)(base + 1);
        if (v.z != 0.f) outIdx[p2] = (ushort)(base + 2);
        if (v.w != 0.f) outIdx[p3] = (ushort)(base + 3);
        cnt += t0 + t1 + t2 + t3;
    }
    int cpad = (cnt + 7) & ~7;
    if (lane < cpad - cnt) outIdx[cnt + lane] = (ushort)npad;  // dummy -> zeroed table row
    if (lane == 0) *outNk = cpad >> 3;
}

#define KA_THREADS 256
#define KA_WARPS   8

__global__ void __launch_bounds__(KA_THREADS)
scan_kernel(const float* __restrict__ Se, const float* __restrict__ Si)
{
    int warp = threadIdx.x >> 5;
    int lane = threadIdx.x & 31;
    unsigned lt = (1u << lane) - 1u;
    int gwarp = blockIdx.x * KA_WARPS + warp;
    int totw  = gridDim.x * KA_WARPS;

    for (int row = gwarp; row < T_DATA; row += totw) {
        row_scan<15, 20, 6>((const float4*)(Se + (size_t)row * E_NO), E_NO,
                            g_eidx + (size_t)row * ECAP, g_enk + row, lane, lt);
        row_scan<3, 29, 4>((const float4*)(Si + (size_t)row * I_NO), I_NO,
                           g_iidx + (size_t)row * ICAP, g_ink + row, lane, lt);
    }
}

// ---------------- K-B: table gather (issue-bound, smem-resident weights) ----------------
#define KB_THREADS 1024
#define KB_WARPS   32
#define SH_I_OFF   40032
#define SH_TOTAL_BYTES (50064 * 4)   // 200256

__device__ __forceinline__ float gather_sum(const uint4* __restrict__ ib, int nk,
                                            const float* __restrict__ tab, int jj)
{
    float acc0 = 0.f, acc1 = 0.f;
#pragma unroll 2
    for (int k = 0; k < nk; ++k) {
        uint4 w = ib[k];
        acc0 += tab[(w.x & 0xffffu) * SUB_NO + jj];
        acc1 += tab[(w.x >> 16)     * SUB_NO + jj];
        acc0 += tab[(w.y & 0xffffu) * SUB_NO + jj];
        acc1 += tab[(w.y >> 16)     * SUB_NO + jj];
        acc0 += tab[(w.z & 0xffffu) * SUB_NO + jj];
        acc1 += tab[(w.z >> 16)     * SUB_NO + jj];
        acc0 += tab[(w.w & 0xffffu) * SUB_NO + jj];
        acc1 += tab[(w.w >> 16)     * SUB_NO + jj];
    }
    return acc0 + acc1;
}

__global__ void __launch_bounds__(KB_THREADS, 1)
gather_kernel()
{
    extern __shared__ float sh[];
    float* sh_e = sh;
    float* sh_i = sh + SH_I_OFF;
    {
        const float4* se4 = (const float4*)g_CTe;
        const float4* si4 = (const float4*)g_CTi;
        float4* de = (float4*)sh_e;
        float4* di = (float4*)sh_i;
        for (int i = threadIdx.x; i < (E_NO * SUB_NO) / 4; i += KB_THREADS) de[i] = se4[i];
        for (int i = threadIdx.x; i < (I_NO * SUB_NO) / 4; i += KB_THREADS) di[i] = si4[i];
        if (threadIdx.x < 32) sh_e[E_NO * SUB_NO + threadIdx.x] = 0.f;  // pad row 2000
        if (threadIdx.x < 32) sh_i[I_NO * SUB_NO + threadIdx.x] = 0.f;  // pad row 500
    }
    __syncthreads();

    int warp = threadIdx.x >> 5;
    int lane = threadIdx.x & 31;
    int jj = (lane < SUB_NO) ? lane : 0;
    int gwarp = blockIdx.x * KB_WARPS + warp;
    int totw  = gridDim.x * KB_WARPS;

    for (int row = gwarp; row < T_DATA; row += totw) {
        int enk = g_enk[row];
        int ink = g_ink[row];
        float ae = gather_sum((const uint4*)(g_eidx + (size_t)row * ECAP), enk, sh_e, jj);
        float ai = gather_sum((const uint4*)(g_iidx + (size_t)row * ICAP), ink, sh_i, jj);
        if (lane < SUB_NO) {
            g_synZe[(PAD + row) * SUB_NO + lane] = ae;
            g_synZi[(PAD + row) * SUB_NO + lane] = ai;
        }
    }
}

// ---------------- K3: fully-unrolled ring-prefetched IIR ----------------
#define CH   32
#define NCH  (T_DATA / CH)    // 625  (20000 % 32 == 0)
#define NIT  (PAD + CH)       // 128 iterations, compile-time constant
#define RD   16               // prefetch ring depth

__global__ void __launch_bounds__(128)
iir_kernel()
{
    int tid = blockIdx.x * blockDim.x + threadIdx.x;
    if (tid >= 2 * NCH * SUB_NO) return;
    int type  = (tid >= NCH * SUB_NO);
    int q     = tid - type * NCH * SUB_NO;
    int s     = q % SUB_NO;
    int chunk = q / SUB_NO;

    const float* __restrict__ x = (type ? g_synZi : g_synZe) + chunk * CH * SUB_NO + s;
    float*       __restrict__ y = (type ? g_f1    : g_f0   ) + chunk * CH * SUB_NO + s;
    float r  = g_par[(type ? P_RI  : P_RE ) + s];
    float B  = g_par[(type ? P_BI  : P_BE ) + s];
    float BD = g_par[(type ? P_BDI : P_BDE) + s];
    float C1 = g_par[(type ? P_C1I : P_C1E) + s];

    float ring[RD];
#pragma unroll
    for (int p = 0; p < RD; ++p) ring[p] = x[p * SUB_NO];

    float s1 = 0.f, s2 = 0.f, xp = 0.f;
#pragma unroll
    for (int k = 0; k < NIT; ++k) {
        float xv = ring[k % RD];
        if (k + RD < NIT) ring[k % RD] = x[(k + RD) * SUB_NO];
        float ns2 = r * (s1 + s2);
        s1 = fmaf(r, s1, xv);
        s2 = ns2;
        if (k >= PAD)
            y[(k - PAD) * SUB_NO] = B * s2 - BD * s1 + BD * xv + C1 * xp;
        xp = xv;
    }
}

// ---------------- K4: per-timestep subunit tree + V ----------------
__device__ __forceinline__ float fast_tanh(float x)
{
    x = fminf(fmaxf(x, -15.f), 15.f);
    float e = __expf(2.f * x);
    return __fdividef(e - 1.f, e + 1.f);
}

__global__ void tree_kernel(float* __restrict__ out)
{
    int t = blockIdx.x * blockDim.x + threadIdx.x;
    if (t >= T_DATA) return;

    float syn[SUB_NO];
    const float4* p0 = (const float4*)(g_f0 + t * SUB_NO);
    const float4* p1 = (const float4*)(g_f1 + t * SUB_NO);
#pragma unroll
    for (int q = 0; q < 5; ++q) {
        float4 a = p0[q];
        float4 b = p1[q];
        syn[4 * q]     = a.x + b.x;
        syn[4 * q + 1] = a.y + b.y;
        syn[4 * q + 2] = a.z + b.z;
        syn[4 * q + 3] = a.w + b.w;
    }
    float gain[SUB_NO], th[SUB_NO];
#pragma unroll
    for (int j = 0; j < SUB_NO; ++j) { gain[j] = g_par[P_GAIN + j]; th[j] = g_par[P_THETA + j]; }

    float sub[SUB_NO];
#pragma unroll
    for (int i = SUB_NO - 1; i >= 0; --i) {
        float v = syn[i] + th[i];
        if (2 * i + 1 < SUB_NO) v = fmaf(gain[2 * i + 1], sub[2 * i + 1], v);
        if (2 * i + 2 < SUB_NO) v = fmaf(gain[2 * i + 2], sub[2 * i + 2], v);
        sub[i] = fast_tanh(v);
    }
    out[t] = fmaf(sub[0], gain[0], g_par[P_VO]);
}

// ---------------- launch ----------------
extern "C" void kernel_launch(void* const* d_in, const int* in_sizes, int n_in,
                              void* d_out, int out_size)
{
    const float* Se     = (const float*)d_in[0];
    const float* Si     = (const float*)d_in[1];
    const float* Wsyn   = (const float*)d_in[3];
    const float* Tausyn = (const float*)d_in[4];
    const float* Dsyn   = (const float*)d_in[5];
    const float* Wsub   = (const float*)d_in[6];
    const float* Vo     = (const float*)d_in[7];
    const float* Theta  = (const float*)d_in[8];
    const float* Ce     = (const float*)d_in[9];
    const float* Ci     = (const float*)d_in[10];
    float* out = (float*)d_out;

    int prep_threads = E_NO + I_NO + 40 * T_NO + SUB_NO + 1;  // 10561
    prep_kernel<<<(prep_threads + 255) / 256, 256>>>(Ce, Ci, Wsyn, Tausyn, Dsyn, Wsub, Vo, Theta, out);

    scan_kernel<<<1184, KA_THREADS>>>(Se, Si);

    cudaFuncSetAttribute(gather_kernel, cudaFuncAttributeMaxDynamicSharedMemorySize, SH_TOTAL_BYTES);
    gather_kernel<<<148, KB_THREADS, SH_TOTAL_BYTES>>>();

    iir_kernel<<<(2 * NCH * SUB_NO + 127) / 128, 128>>>();
    tree_kernel<<<(T_DATA + 127) / 128, 128>>>(out);
}

// round 7
// speedup vs baseline: 1.4930x; 1.0451x over previous
#include <cuda_runtime.h>
#include <math.h>

#define SUB_NO 20
#define T_NO 201
#define E_NO 2000
#define I_NO 500
#define T_DATA 20000

// Output layout: concat of (V[20000], out_filters[40*201], C_syn_e[20*2000], C_syn_i[20*500])
#define OFF_V  0
#define OFF_F  (T_DATA)                   // 20000
#define OFF_CE (OFF_F + 40 * T_NO)        // 28040
#define OFF_CI (OFF_CE + SUB_NO * E_NO)   // 68040

#define PAD 96   // IIR warm-up: r^96 <= 1e-12 relative, far below 1e-3 tolerance

// ---------------- scratch ----------------
__device__ float g_CTe[E_NO * SUB_NO];
__device__ float g_CTi[I_NO * SUB_NO];
__device__ float g_synZe[(PAD + T_DATA) * SUB_NO];  // zero-padded head, then syn_e
__device__ float g_synZi[(PAD + T_DATA) * SUB_NO];

// compact spike indices (scan output)
#define ECAP 288                 // 36 uint4 groups
#define ICAP 96                  // 12 uint4 groups
#define EGMAX 36
#define IGMAX 12
__device__ ushort g_eidx[(size_t)T_DATA * ECAP];
__device__ ushort g_iidx[(size_t)T_DATA * ICAP];
__device__ int    g_enk[T_DATA];
__device__ int    g_ink[T_DATA];

// param pack
#define P_GAIN  0
#define P_THETA 32
#define P_RE    64
#define P_BE    96
#define P_BDE   128
#define P_C1E   160
#define P_RI    192
#define P_BI    224
#define P_BDI   256
#define P_C1I   288
#define P_VO    320
__device__ float g_par[336];

// ---------------- prep work (runs inside scan kernel's first PREP_BLOCKS) ----------------
__device__ __forceinline__ void do_prep(int tid,
                                        const float* __restrict__ Craw_e,
                                        const float* __restrict__ Craw_i,
                                        const float* __restrict__ Wsyn,
                                        const float* __restrict__ Tausyn,
                                        const float* __restrict__ Dsyn,
                                        const float* __restrict__ Wsub,
                                        const float* __restrict__ Vo,
                                        const float* __restrict__ Theta,
                                        float* __restrict__ out)
{
    if (tid < PAD * SUB_NO) {
        g_synZe[tid] = 0.f;
        g_synZi[tid] = 0.f;
    }

    if (tid < E_NO + I_NO) {
        const float* raw;
        float* o;
        float* ct;
        int stride, e;
        if (tid < E_NO) { raw = Craw_e; o = out + OFF_CE; ct = g_CTe; stride = E_NO; e = tid; }
        else            { raw = Craw_i; o = out + OFF_CI; ct = g_CTi; stride = I_NO; e = tid - E_NO; }
        float v[SUB_NO];
        float m = -1e30f;
#pragma unroll
        for (int j = 0; j < SUB_NO; ++j) { v[j] = raw[j * stride + e]; m = fmaxf(m, v[j]); }
        float s = 0.f;
#pragma unroll
        for (int j = 0; j < SUB_NO; ++j) { v[j] = expf(v[j] - m); s += v[j]; }
        float inv = 1.f / s;
#pragma unroll
        for (int j = 0; j < SUB_NO; ++j) {
            float w = v[j] * inv;
            o[j * stride + e]  = w;
            ct[e * SUB_NO + j] = w;
        }
    }

    int f = tid - (E_NO + I_NO);
    if (f >= 0 && f < 40 * T_NO) {
        int row  = f / T_NO;
        int k    = f - row * T_NO;
        int type = row / SUB_NO;
        int s    = row - type * SUB_NO;
        float delta = expf(Dsyn[s * 2 + type]);
        float tau   = expf(Tausyn[s * 2 + type]);
        float w     = expf(Wsyn[s * 2 + type]);
        float tt    = fmaxf((float)k - delta, 0.f) / tau;
        float val   = tt * expf(-tt) * w;
        if (type) val = -val;
        out[OFF_F + row * T_NO + k] = val;
    }

    int p = tid - (E_NO + I_NO + 40 * T_NO);
    if (p >= 0 && p < SUB_NO) {
        g_par[P_GAIN  + p] = expf(Wsub[p]);
        g_par[P_THETA + p] = Theta[p];
#pragma unroll
        for (int type = 0; type < 2; ++type) {
            float delta = expf(Dsyn[p * 2 + type]);
            float tau   = expf(Tausyn[p * 2 + type]);
            float w     = expf(Wsyn[p * 2 + type]);
            float r     = expf(-1.f / tau);
            float B     = w * expf(delta / tau) / tau;
            if (type) B = -B;
            float c1 = (delta > 1.f) ? B * (delta - 1.f) * r : 0.f;
            g_par[(type ? P_RI  : P_RE ) + p] = r;
            g_par[(type ? P_BI  : P_BE ) + p] = B;
            g_par[(type ? P_BDI : P_BDE) + p] = B * delta;
            g_par[(type ? P_C1I : P_C1E) + p] = c1;
        }
    }
    if (tid == E_NO + I_NO + 40 * T_NO + SUB_NO) g_par[P_VO] = Vo[0];
}

// ---------------- K-A: streaming scan/compaction (+ prep blocks) ----------------
template<int NFULL, int TAIL, int PF>
__device__ __forceinline__ void row_scan(const float4* __restrict__ Sv, int npad,
                                         ushort* __restrict__ outIdx, int* __restrict__ outNk,
                                         int lane, unsigned lt)
{
    constexpr int NT = NFULL + 1;
    const float4 z4 = make_float4(0.f, 0.f, 0.f, 0.f);
    float4 ring[PF];
#pragma unroll
    for (int p = 0; p < PF; ++p) {
        if (p < NT) ring[p] = (p < NFULL || lane < TAIL) ? Sv[p * 32 + lane] : z4;
        else        ring[p] = z4;
    }
    int cnt = 0;
#pragma unroll
    for (int it = 0; it < NT; ++it) {
        float4 v = ring[it % PF];
        if (it + PF < NT)
            ring[it % PF] = ((it + PF) < NFULL || lane < TAIL) ? Sv[(it + PF) * 32 + lane] : z4;
        unsigned m0 = __ballot_sync(0xffffffffu, v.x != 0.f);
        unsigned m1 = __ballot_sync(0xffffffffu, v.y != 0.f);
        unsigned m2 = __ballot_sync(0xffffffffu, v.z != 0.f);
        unsigned m3 = __ballot_sync(0xffffffffu, v.w != 0.f);
        int t0 = __popc(m0), t1 = __popc(m1), t2 = __popc(m2), t3 = __popc(m3);
        int p0 = cnt + __popc(m0 & lt);
        int p1 = cnt + t0 + __popc(m1 & lt);
        int p2 = cnt + t0 + t1 + __popc(m2 & lt);
        int p3 = cnt + t0 + t1 + t2 + __popc(m3 & lt);
        int base = (it * 32 + lane) * 4;
        if (v.x != 0.f) outIdx[p0] = (ushort)(base);
        if (v.y != 0.f) outIdx[p1] = (ushort)(base + 1);
        if (v.z != 0.f) outIdx[p2] = (ushort)(base + 2);
        if (v.w != 0.f) outIdx[p3] = (ushort)(base + 3);
        cnt += t0 + t1 + t2 + t3;
    }
    int cpad = (cnt + 7) & ~7;
    if (lane < cpad - cnt) outIdx[cnt + lane] = (ushort)npad;  // dummy -> zeroed table row
    if (lane == 0) *outNk = cpad >> 3;
}

#define KA_THREADS 256
#define KA_WARPS   8
#define PREP_BLOCKS 42
#define SCAN_BLOCKS 1184

__global__ void __launch_bounds__(KA_THREADS)
scan_kernel(const float* __restrict__ Se, const float* __restrict__ Si,
            const float* __restrict__ Craw_e, const float* __restrict__ Craw_i,
            const float* __restrict__ Wsyn, const float* __restrict__ Tausyn,
            const float* __restrict__ Dsyn, const float* __restrict__ Wsub,
            const float* __restrict__ Vo, const float* __restrict__ Theta,
            float* __restrict__ out)
{
    if (blockIdx.x < PREP_BLOCKS) {
        do_prep(blockIdx.x * KA_THREADS + threadIdx.x,
                Craw_e, Craw_i, Wsyn, Tausyn, Dsyn, Wsub, Vo, Theta, out);
        return;
    }
    int b = blockIdx.x - PREP_BLOCKS;
    int warp = threadIdx.x >> 5;
    int lane = threadIdx.x & 31;
    unsigned lt = (1u << lane) - 1u;
    int gwarp = b * KA_WARPS + warp;
    int totw  = SCAN_BLOCKS * KA_WARPS;

    for (int row = gwarp; row < T_DATA; row += totw) {
        row_scan<15, 20, 6>((const float4*)(Se + (size_t)row * E_NO), E_NO,
                            g_eidx + (size_t)row * ECAP, g_enk + row, lane, lt);
        row_scan<3, 29, 4>((const float4*)(Si + (size_t)row * I_NO), I_NO,
                           g_iidx + (size_t)row * ICAP, g_ink + row, lane, lt);
    }
}

// ---------------- K-B: table gather with index ring-prefetch ----------------
#define KB_THREADS 1024
#define KB_WARPS   32
#define SH_I_OFF   40032
#define SH_TOTAL_BYTES (50064 * 4)   // 200256

// GMAX = total valid uint4 groups in the row buffer (memory always valid).
// Prefetch is clamped to GMAX-1; garbage indices are never consumed because
// a ring slot loaded at k is only used at iteration k+4 (< nk).
template<int GMAX>
__device__ __forceinline__ float gather_sum(const uint4* __restrict__ ib, int nk,
                                            const float* __restrict__ tab, int jj)
{
    float acc0 = 0.f, acc1 = 0.f;
    uint4 ring[4];
#pragma unroll
    for (int p = 0; p < 4; ++p) ring[p] = ib[min(p, GMAX - 1)];
#pragma unroll 4
    for (int k = 0; k < nk; ++k) {
        uint4 w = ring[k & 3];
        ring[k & 3] = ib[min(k + 4, GMAX - 1)];
        acc0 += tab[(w.x & 0xffffu) * SUB_NO + jj];
        acc1 += tab[(w.x >> 16)     * SUB_NO + jj];
        acc0 += tab[(w.y & 0xffffu) * SUB_NO + jj];
        acc1 += tab[(w.y >> 16)     * SUB_NO + jj];
        acc0 += tab[(w.z & 0xffffu) * SUB_NO + jj];
        acc1 += tab[(w.z >> 16)     * SUB_NO + jj];
        acc0 += tab[(w.w & 0xffffu) * SUB_NO + jj];
        acc1 += tab[(w.w >> 16)     * SUB_NO + jj];
    }
    return acc0 + acc1;
}

__global__ void __launch_bounds__(KB_THREADS, 1)
gather_kernel()
{
    extern __shared__ float sh[];
    float* sh_e = sh;
    float* sh_i = sh + SH_I_OFF;
    {
        const float4* se4 = (const float4*)g_CTe;
        const float4* si4 = (const float4*)g_CTi;
        float4* de = (float4*)sh_e;
        float4* di = (float4*)sh_i;
        for (int i = threadIdx.x; i < (E_NO * SUB_NO) / 4; i += KB_THREADS) de[i] = se4[i];
        for (int i = threadIdx.x; i < (I_NO * SUB_NO) / 4; i += KB_THREADS) di[i] = si4[i];
        if (threadIdx.x < 32) sh_e[E_NO * SUB_NO + threadIdx.x] = 0.f;  // pad row 2000
        if (threadIdx.x < 32) sh_i[I_NO * SUB_NO + threadIdx.x] = 0.f;  // pad row 500
    }
    __syncthreads();

    int warp = threadIdx.x >> 5;
    int lane = threadIdx.x & 31;
    int jj = (lane < SUB_NO) ? lane : 0;
    int gwarp = blockIdx.x * KB_WARPS + warp;
    int totw  = gridDim.x * KB_WARPS;

    for (int row = gwarp; row < T_DATA; row += totw) {
        int enk = g_enk[row];
        int ink = g_ink[row];
        float ae = gather_sum<EGMAX>((const uint4*)(g_eidx + (size_t)row * ECAP), enk, sh_e, jj);
        float ai = gather_sum<IGMAX>((const uint4*)(g_iidx + (size_t)row * ICAP), ink, sh_i, jj);
        if (lane < SUB_NO) {
            g_synZe[(PAD + row) * SUB_NO + lane] = ae;
            g_synZi[(PAD + row) * SUB_NO + lane] = ai;
        }
    }
}

// ---------------- K-C: fused IIR + tree (smem staged, no global round-trip) ----------------
#define CHU  32
#define NCH  (T_DATA / CHU)    // 625
#define NIT  (PAD + CHU)       // 128, compile-time
#define RD   16
#define PAIRS_PER_BLK 8        // 8 chunks/block, 2 warps (E,I) per chunk
#define IT_THREADS (PAIRS_PER_BLK * 64)  // 512

__device__ __forceinline__ float fast_tanh(float x)
{
    x = fminf(fmaxf(x, -15.f), 15.f);
    float e = __expf(2.f * x);
    return __fdividef(e - 1.f, e + 1.f);
}

__global__ void __launch_bounds__(IT_THREADS)
iirtree_kernel(float* __restrict__ out)
{
    __shared__ float syn2[PAIRS_PER_BLK][2][CHU][21];   // pad 21: conflict-free
    int w    = threadIdx.x >> 6;          // chunk pair 0..7
    int type = (threadIdx.x >> 5) & 1;    // E / I warp
    int lane = threadIdx.x & 31;
    int chunk = blockIdx.x * PAIRS_PER_BLK + w;

    if (chunk < NCH && lane < SUB_NO) {
        int s = lane;
        const float* __restrict__ x = (type ? g_synZi : g_synZe) + chunk * CHU * SUB_NO + s;
        float r  = g_par[(type ? P_RI  : P_RE ) + s];
        float B  = g_par[(type ? P_BI  : P_BE ) + s];
        float BD = g_par[(type ? P_BDI : P_BDE) + s];
        float C1 = g_par[(type ? P_C1I : P_C1E) + s];

        float ring[RD];
#pragma unroll
        for (int p = 0; p < RD; ++p) ring[p] = x[p * SUB_NO];

        float s1 = 0.f, s2 = 0.f, xp = 0.f;
#pragma unroll
        for (int k = 0; k < NIT; ++k) {
            float xv = ring[k % RD];
            if (k + RD < NIT) ring[k % RD] = x[(k + RD) * SUB_NO];
            float ns2 = r * (s1 + s2);
            s1 = fmaf(r, s1, xv);
            s2 = ns2;
            if (k >= PAD)
                syn2[w][type][k - PAD][s] = B * s2 - BD * s1 + BD * xv + C1 * xp;
            xp = xv;
        }
    }
    __syncthreads();

    if (chunk < NCH && type == 0) {
        int t = chunk * CHU + lane;       // lane = local timestep, all 32 valid
        float syn[SUB_NO];
#pragma unroll
        for (int s = 0; s < SUB_NO; ++s)
            syn[s] = syn2[w][0][lane][s] + syn2[w][1][lane][s];

        float gain[SUB_NO], th[SUB_NO];
#pragma unroll
        for (int j = 0; j < SUB_NO; ++j) { gain[j] = g_par[P_GAIN + j]; th[j] = g_par[P_THETA + j]; }

        float sub[SUB_NO];
#pragma unroll
        for (int i = SUB_NO - 1; i >= 0; --i) {
            float v = syn[i] + th[i];
            if (2 * i + 1 < SUB_NO) v = fmaf(gain[2 * i + 1], sub[2 * i + 1], v);
            if (2 * i + 2 < SUB_NO) v = fmaf(gain[2 * i + 2], sub[2 * i + 2], v);
            sub[i] = fast_tanh(v);
        }
        out[t] = fmaf(sub[0], gain[0], g_par[P_VO]);
    }
}

// ---------------- launch ----------------
extern "C" void kernel_launch(void* const* d_in, const int* in_sizes, int n_in,
                              void* d_out, int out_size)
{
    const float* Se     = (const float*)d_in[0];
    const float* Si     = (const float*)d_in[1];
    const float* Wsyn   = (const float*)d_in[3];
    const float* Tausyn = (const float*)d_in[4];
    const float* Dsyn   = (const float*)d_in[5];
    const float* Wsub   = (const float*)d_in[6];
    const float* Vo     = (const float*)d_in[7];
    const float* Theta  = (const float*)d_in[8];
    const float* Ce     = (const float*)d_in[9];
    const float* Ci     = (const float*)d_in[10];
    float* out = (float*)d_out;

    scan_kernel<<<PREP_BLOCKS + SCAN_BLOCKS, KA_THREADS>>>(
        Se, Si, Ce, Ci, Wsyn, Tausyn, Dsyn, Wsub, Vo, Theta, out);

    cudaFuncSetAttribute(gather_kernel, cudaFuncAttributeMaxDynamicSharedMemorySize, SH_TOTAL_BYTES);
    gather_kernel<<<148, KB_THREADS, SH_TOTAL_BYTES>>>();

    iirtree_kernel<<<(NCH + PAIRS_PER_BLK - 1) / PAIRS_PER_BLK, IT_THREADS>>>(out);
}

// round 8
// speedup vs baseline: 1.7770x; 1.1902x over previous
#include <cuda_runtime.h>
#include <math.h>

#define SUB_NO 20
#define T_NO 201
#define E_NO 2000
#define I_NO 500
#define T_DATA 20000

// Output layout: concat of (V[20000], out_filters[40*201], C_syn_e[20*2000], C_syn_i[20*500])
#define OFF_V  0
#define OFF_F  (T_DATA)                   // 20000
#define OFF_CE (OFF_F + 40 * T_NO)        // 28040
#define OFF_CI (OFF_CE + SUB_NO * E_NO)   // 68040

#define PAD 96      // IIR warm-up: r^96 <= 1e-12 relative, far below 1e-3 tolerance
#define TSTR 32     // padded table row stride (floats): aligned, shift addressing

// ---------------- scratch ----------------
__device__ float g_TEp[(E_NO + 1) * TSTR];          // padded softmax tables (+ zeroed dummy row)
__device__ float g_TIp[(I_NO + 1) * TSTR];
__device__ float g_synZe[(PAD + T_DATA) * SUB_NO];  // zero-padded head, then syn_e
__device__ float g_synZi[(PAD + T_DATA) * SUB_NO];

// param pack
#define P_GAIN  0
#define P_THETA 32
#define P_RE    64
#define P_BE    96
#define P_BDE   128
#define P_C1E   160
#define P_RI    192
#define P_BI    224
#define P_BDI   256
#define P_C1I   288
#define P_VO    320
__device__ float g_par[336];

// ---------------- K1: prep (softmax tables, filters, IIR params, zero pads) ----------------
__global__ void prep_kernel(const float* __restrict__ Craw_e,
                            const float* __restrict__ Craw_i,
                            const float* __restrict__ Wsyn,
                            const float* __restrict__ Tausyn,
                            const float* __restrict__ Dsyn,
                            const float* __restrict__ Wsub,
                            const float* __restrict__ Vo,
                            const float* __restrict__ Theta,
                            float* __restrict__ out)
{
    int tid = blockIdx.x * blockDim.x + threadIdx.x;

    if (tid < PAD * SUB_NO) {
        g_synZe[tid] = 0.f;
        g_synZi[tid] = 0.f;
    }
    if (tid < TSTR) {                      // zero dummy rows (gather padding target)
        g_TEp[E_NO * TSTR + tid] = 0.f;
        g_TIp[I_NO * TSTR + tid] = 0.f;
    }

    if (tid < E_NO + I_NO) {
        const float* raw;
        float* o;
        float* tp;
        int stride, e;
        if (tid < E_NO) { raw = Craw_e; o = out + OFF_CE; tp = g_TEp; stride = E_NO; e = tid; }
        else            { raw = Craw_i; o = out + OFF_CI; tp = g_TIp; stride = I_NO; e = tid - E_NO; }
        float v[SUB_NO];
        float m = -1e30f;
#pragma unroll
        for (int j = 0; j < SUB_NO; ++j) { v[j] = raw[j * stride + e]; m = fmaxf(m, v[j]); }
        float s = 0.f;
#pragma unroll
        for (int j = 0; j < SUB_NO; ++j) { v[j] = expf(v[j] - m); s += v[j]; }
        float inv = 1.f / s;
#pragma unroll
        for (int j = 0; j < SUB_NO; ++j) {
            float w = v[j] * inv;
            o[j * stride + e]  = w;
            tp[e * TSTR + j]   = w;
        }
    }

    int f = tid - (E_NO + I_NO);
    if (f >= 0 && f < 40 * T_NO) {
        int row  = f / T_NO;
        int k    = f - row * T_NO;
        int type = row / SUB_NO;
        int s    = row - type * SUB_NO;
        float delta = expf(Dsyn[s * 2 + type]);
        float tau   = expf(Tausyn[s * 2 + type]);
        float w     = expf(Wsyn[s * 2 + type]);
        float tt    = fmaxf((float)k - delta, 0.f) / tau;
        float val   = tt * expf(-tt) * w;
        if (type) val = -val;
        out[OFF_F + row * T_NO + k] = val;
    }

    int p = tid - (E_NO + I_NO + 40 * T_NO);
    if (p >= 0 && p < SUB_NO) {
        g_par[P_GAIN  + p] = expf(Wsub[p]);
        g_par[P_THETA + p] = Theta[p];
#pragma unroll
        for (int type = 0; type < 2; ++type) {
            float delta = expf(Dsyn[p * 2 + type]);
            float tau   = expf(Tausyn[p * 2 + type]);
            float w     = expf(Wsyn[p * 2 + type]);
            float r     = expf(-1.f / tau);
            float B     = w * expf(delta / tau) / tau;
            if (type) B = -B;
            float c1 = (delta > 1.f) ? B * (delta - 1.f) * r : 0.f;
            g_par[(type ? P_RI  : P_RE ) + p] = r;
            g_par[(type ? P_BI  : P_BE ) + p] = B;
            g_par[(type ? P_BDI : P_BDE) + p] = B * delta;
            g_par[(type ? P_C1I : P_C1E) + p] = c1;
        }
    }
    if (tid == E_NO + I_NO + 40 * T_NO + SUB_NO) g_par[P_VO] = Vo[0];
}

// ---------------- K2: fused scan + L2-gather (one kernel, no idx round-trip) ----------------
// scan: NFULL full 32-lane float4 iters + tail (TAIL lanes), PF-deep LDG ring.
// Compacts nonzero indices into the per-warp smem buffer; returns #uint4 groups.
template<int NFULL, int TAIL, int PF>
__device__ __forceinline__ int row_scan(const float4* __restrict__ Sv, int npad,
                                        ushort* __restrict__ idxb,
                                        int lane, unsigned lt)
{
    constexpr int NT = NFULL + 1;
    const float4 z4 = make_float4(0.f, 0.f, 0.f, 0.f);
    float4 ring[PF];
#pragma unroll
    for (int p = 0; p < PF; ++p) {
        if (p < NT) ring[p] = (p < NFULL || lane < TAIL) ? Sv[p * 32 + lane] : z4;
        else        ring[p] = z4;
    }
    int cnt = 0;
#pragma unroll
    for (int it = 0; it < NT; ++it) {
        float4 v = ring[it % PF];
        if (it + PF < NT)
            ring[it % PF] = ((it + PF) < NFULL || lane < TAIL) ? Sv[(it + PF) * 32 + lane] : z4;
        unsigned m0 = __ballot_sync(0xffffffffu, v.x != 0.f);
        unsigned m1 = __ballot_sync(0xffffffffu, v.y != 0.f);
        unsigned m2 = __ballot_sync(0xffffffffu, v.z != 0.f);
        unsigned m3 = __ballot_sync(0xffffffffu, v.w != 0.f);
        int t0 = __popc(m0), t1 = __popc(m1), t2 = __popc(m2), t3 = __popc(m3);
        int p0 = cnt + __popc(m0 & lt);
        int p1 = cnt + t0 + __popc(m1 & lt);
        int p2 = cnt + t0 + t1 + __popc(m2 & lt);
        int p3 = cnt + t0 + t1 + t2 + __popc(m3 & lt);
        int base = (it * 32 + lane) * 4;
        if (v.x != 0.f) idxb[p0] = (ushort)(base);
        if (v.y != 0.f) idxb[p1] = (ushort)(base + 1);
        if (v.z != 0.f) idxb[p2] = (ushort)(base + 2);
        if (v.w != 0.f) idxb[p3] = (ushort)(base + 3);
        cnt += t0 + t1 + t2 + t3;
    }
    int cpad = (cnt + 7) & ~7;
    if (lane < cpad - cnt) idxb[cnt + lane] = (ushort)npad;  // dummy -> zeroed table row
    return cpad >> 3;
}

// gather from the L2-resident padded table: per nonzero, a lane-coalesced
// 80B LDG (tab row) hit in L2; unroll gives MLP ~16.
__device__ __forceinline__ float gather_g(const uint4* __restrict__ ib, int nk,
                                          const float* __restrict__ tab, int jj)
{
    float a0 = 0.f, a1 = 0.f;
#pragma unroll 2
    for (int k = 0; k < nk; ++k) {
        uint4 w = ib[k];
        a0 += __ldg(tab + ((w.x & 0xffffu) * TSTR + jj));
        a1 += __ldg(tab + ((w.x >> 16)     * TSTR + jj));
        a0 += __ldg(tab + ((w.y & 0xffffu) * TSTR + jj));
        a1 += __ldg(tab + ((w.y >> 16)     * TSTR + jj));
        a0 += __ldg(tab + ((w.z & 0xffffu) * TSTR + jj));
        a1 += __ldg(tab + ((w.z >> 16)     * TSTR + jj));
        a0 += __ldg(tab + ((w.w & 0xffffu) * TSTR + jj));
        a1 += __ldg(tab + ((w.w >> 16)     * TSTR + jj));
    }
    return a0 + a1;
}

#define K2_THREADS 256
#define K2_WARPS   8
#define K2_BLOCKS  (148 * 4)   // exactly one wave at 4 CTAs/SM

__global__ void __launch_bounds__(K2_THREADS, 4)
spike_kernel(const float* __restrict__ Se, const float* __restrict__ Si)
{
    __shared__ __align__(16) ushort idx_s[K2_WARPS][272];   // 544B per warp
    int warp = threadIdx.x >> 5;
    int lane = threadIdx.x & 31;
    unsigned lt = (1u << lane) - 1u;
    int jj = (lane < SUB_NO) ? lane : 0;
    ushort* idxb = idx_s[warp];

    int gwarp = blockIdx.x * K2_WARPS + warp;
    int totw  = K2_BLOCKS * K2_WARPS;

    for (int row = gwarp; row < T_DATA; row += totw) {
        // ---- E: scan + gather ----
        int enk = row_scan<15, 20, 5>((const float4*)(Se + (size_t)row * E_NO), E_NO,
                                      idxb, lane, lt);
        __syncwarp();
        float ae = gather_g((const uint4*)idxb, enk, g_TEp, jj);
        __syncwarp();

        // ---- I: scan + gather ----
        int ink = row_scan<3, 29, 3>((const float4*)(Si + (size_t)row * I_NO), I_NO,
                                     idxb, lane, lt);
        __syncwarp();
        float ai = gather_g((const uint4*)idxb, ink, g_TIp, jj);
        __syncwarp();

        if (lane < SUB_NO) {
            g_synZe[(PAD + row) * SUB_NO + lane] = ae;
            g_synZi[(PAD + row) * SUB_NO + lane] = ai;
        }
    }
}

// ---------------- K3: fused IIR + tree (smem staged) ----------------
#define CHU  32
#define NCH  (T_DATA / CHU)    // 625
#define NIT  (PAD + CHU)       // 128, compile-time
#define RD   16
#define PAIRS_PER_BLK 8
#define IT_THREADS (PAIRS_PER_BLK * 64)  // 512

__device__ __forceinline__ float fast_tanh(float x)
{
    x = fminf(fmaxf(x, -15.f), 15.f);
    float e = __expf(2.f * x);
    return __fdividef(e - 1.f, e + 1.f);
}

__global__ void __launch_bounds__(IT_THREADS)
iirtree_kernel(float* __restrict__ out)
{
    __shared__ float syn2[PAIRS_PER_BLK][2][CHU][21];
    int w    = threadIdx.x >> 6;
    int type = (threadIdx.x >> 5) & 1;
    int lane = threadIdx.x & 31;
    int chunk = blockIdx.x * PAIRS_PER_BLK + w;

    if (chunk < NCH && lane < SUB_NO) {
        int s = lane;
        const float* __restrict__ x = (type ? g_synZi : g_synZe) + chunk * CHU * SUB_NO + s;
        float r  = g_par[(type ? P_RI  : P_RE ) + s];
        float B  = g_par[(type ? P_BI  : P_BE ) + s];
        float BD = g_par[(type ? P_BDI : P_BDE) + s];
        float C1 = g_par[(type ? P_C1I : P_C1E) + s];

        float ring[RD];
#pragma unroll
        for (int p = 0; p < RD; ++p) ring[p] = x[p * SUB_NO];

        float s1 = 0.f, s2 = 0.f, xp = 0.f;
#pragma unroll
        for (int k = 0; k < NIT; ++k) {
            float xv = ring[k % RD];
            if (k + RD < NIT) ring[k % RD] = x[(k + RD) * SUB_NO];
            float ns2 = r * (s1 + s2);
            s1 = fmaf(r, s1, xv);
            s2 = ns2;
            if (k >= PAD)
                syn2[w][type][k - PAD][s] = B * s2 - BD * s1 + BD * xv + C1 * xp;
            xp = xv;
        }
    }
    __syncthreads();

    if (chunk < NCH && type == 0) {
        int t = chunk * CHU + lane;
        float syn[SUB_NO];
#pragma unroll
        for (int s = 0; s < SUB_NO; ++s)
            syn[s] = syn2[w][0][lane][s] + syn2[w][1][lane][s];

        float gain[SUB_NO], th[SUB_NO];
#pragma unroll
        for (int j = 0; j < SUB_NO; ++j) { gain[j] = g_par[P_GAIN + j]; th[j] = g_par[P_THETA + j]; }

        float sub[SUB_NO];
#pragma unroll
        for (int i = SUB_NO - 1; i >= 0; --i) {
            float v = syn[i] + th[i];
            if (2 * i + 1 < SUB_NO) v = fmaf(gain[2 * i + 1], sub[2 * i + 1], v);
            if (2 * i + 2 < SUB_NO) v = fmaf(gain[2 * i + 2], sub[2 * i + 2], v);
            sub[i] = fast_tanh(v);
        }
        out[t] = fmaf(sub[0], gain[0], g_par[P_VO]);
    }
}

// ---------------- launch ----------------
extern "C" void kernel_launch(void* const* d_in, const int* in_sizes, int n_in,
                              void* d_out, int out_size)
{
    const float* Se     = (const float*)d_in[0];
    const float* Si     = (const float*)d_in[1];
    const float* Wsyn   = (const float*)d_in[3];
    const float* Tausyn = (const float*)d_in[4];
    const float* Dsyn   = (const float*)d_in[5];
    const float* Wsub   = (const float*)d_in[6];
    const float* Vo     = (const float*)d_in[7];
    const float* Theta  = (const float*)d_in[8];
    const float* Ce     = (const float*)d_in[9];
    const float* Ci     = (const float*)d_in[10];
    float* out = (float*)d_out;

    int prep_threads = E_NO + I_NO + 40 * T_NO + SUB_NO + 1;  // 10561
    prep_kernel<<<(prep_threads + 255) / 256, 256>>>(Ce, Ci, Wsyn, Tausyn, Dsyn, Wsub, Vo, Theta, out);

    spike_kernel<<<K2_BLOCKS, K2_THREADS>>>(Se, Si);

    iirtree_kernel<<<(NCH + PAIRS_PER_BLK - 1) / PAIRS_PER_BLK, IT_THREADS>>>(out);
}

// round 9
// speedup vs baseline: 1.8677x; 1.0511x over previous
#include <cuda_runtime.h>
#include <cuda_fp16.h>
#include <math.h>

#define SUB_NO 20
#define T_NO 201
#define E_NO 2000
#define I_NO 500
#define T_DATA 20000

// Output layout: concat of (V[20000], out_filters[40*201], C_syn_e[20*2000], C_syn_i[20*500])
#define OFF_V  0
#define OFF_F  (T_DATA)                   // 20000
#define OFF_CE (OFF_F + 40 * T_NO)        // 28040
#define OFF_CI (OFF_CE + SUB_NO * E_NO)   // 68040

#define PAD 48      // IIR warm-up: r^48 <= 2e-5 rel even at +5sigma tau; tol is 1e-3
#define TSTR 32     // padded table row stride (elements)

// ---------------- scratch ----------------
__device__ __align__(128) __half g_TEh[(E_NO + 1) * TSTR];  // fp16 softmax tables (+ zeroed dummy row)
__device__ __align__(128) __half g_TIh[(I_NO + 1) * TSTR];
__device__ float g_synZe[(PAD + T_DATA) * SUB_NO];          // zero-padded head, then syn_e
__device__ float g_synZi[(PAD + T_DATA) * SUB_NO];
__device__ int   g_done = 0;                                // prep-arrival counter (reset by iirtree)

// param pack
#define P_GAIN  0
#define P_THETA 32
#define P_RE    64
#define P_BE    96
#define P_BDE   128
#define P_C1E   160
#define P_RI    192
#define P_BI    224
#define P_BDI   256
#define P_C1I   288
#define P_VO    320
__device__ float g_par[336];

#define N_PREP (E_NO + I_NO + 40 * T_NO + SUB_NO + 1)   // 10561

// ---------------- prep slice (inlined into spike kernel) ----------------
__device__ void do_prep(int tid,
                        const float* __restrict__ Craw_e,
                        const float* __restrict__ Craw_i,
                        const float* __restrict__ Wsyn,
                        const float* __restrict__ Tausyn,
                        const float* __restrict__ Dsyn,
                        const float* __restrict__ Wsub,
                        const float* __restrict__ Vo,
                        const float* __restrict__ Theta,
                        float* __restrict__ out)
{
    if (tid < PAD * SUB_NO) {
        g_synZe[tid] = 0.f;
        g_synZi[tid] = 0.f;
    }
    if (tid < TSTR) {                      // zero dummy rows (gather padding target)
        g_TEh[E_NO * TSTR + tid] = __float2half(0.f);
        g_TIh[I_NO * TSTR + tid] = __float2half(0.f);
    }

    if (tid < E_NO + I_NO) {
        const float* raw;
        float* o;
        __half* tp;
        int stride, e;
        if (tid < E_NO) { raw = Craw_e; o = out + OFF_CE; tp = g_TEh; stride = E_NO; e = tid; }
        else            { raw = Craw_i; o = out + OFF_CI; tp = g_TIh; stride = I_NO; e = tid - E_NO; }
        float v[SUB_NO];
        float m = -1e30f;
#pragma unroll
        for (int j = 0; j < SUB_NO; ++j) { v[j] = raw[j * stride + e]; m = fmaxf(m, v[j]); }
        float s = 0.f;
#pragma unroll
        for (int j = 0; j < SUB_NO; ++j) { v[j] = expf(v[j] - m); s += v[j]; }
        float inv = 1.f / s;
#pragma unroll
        for (int j = 0; j < SUB_NO; ++j) {
            float w = v[j] * inv;
            o[j * stride + e]  = w;
            tp[e * TSTR + j]   = __float2half(w);
        }
    }

    int f = tid - (E_NO + I_NO);
    if (f >= 0 && f < 40 * T_NO) {
        int row  = f / T_NO;
        int k    = f - row * T_NO;
        int type = row / SUB_NO;
        int s    = row - type * SUB_NO;
        float delta = expf(Dsyn[s * 2 + type]);
        float tau   = expf(Tausyn[s * 2 + type]);
        float w     = expf(Wsyn[s * 2 + type]);
        float tt    = fmaxf((float)k - delta, 0.f) / tau;
        float val   = tt * expf(-tt) * w;
        if (type) val = -val;
        out[OFF_F + row * T_NO + k] = val;
    }

    int p = tid - (E_NO + I_NO + 40 * T_NO);
    if (p >= 0 && p < SUB_NO) {
        g_par[P_GAIN  + p] = expf(Wsub[p]);
        g_par[P_THETA + p] = Theta[p];
#pragma unroll
        for (int type = 0; type < 2; ++type) {
            float delta = expf(Dsyn[p * 2 + type]);
            float tau   = expf(Tausyn[p * 2 + type]);
            float w     = expf(Wsyn[p * 2 + type]);
            float r     = expf(-1.f / tau);
            float B     = w * expf(delta / tau) / tau;
            if (type) B = -B;
            float c1 = (delta > 1.f) ? B * (delta - 1.f) * r : 0.f;
            g_par[(type ? P_RI  : P_RE ) + p] = r;
            g_par[(type ? P_BI  : P_BE ) + p] = B;
            g_par[(type ? P_BDI : P_BDE) + p] = B * delta;
            g_par[(type ? P_C1I : P_C1E) + p] = c1;
        }
    }
    if (tid == N_PREP - 1) g_par[P_VO] = Vo[0];
}

// ---------------- K1: fused prep + scan + L2-gather ----------------
template<int NFULL, int TAIL, int PF>
__device__ __forceinline__ int row_scan(const float4* __restrict__ Sv, int npad,
                                        ushort* __restrict__ idxb,
                                        int lane, unsigned lt)
{
    constexpr int NT = NFULL + 1;
    const float4 z4 = make_float4(0.f, 0.f, 0.f, 0.f);
    float4 ring[PF];
#pragma unroll
    for (int p = 0; p < PF; ++p) {
        if (p < NT) ring[p] = (p < NFULL || lane < TAIL) ? __ldcs(Sv + p * 32 + lane) : z4;
        else        ring[p] = z4;
    }
    int cnt = 0;
#pragma unroll
    for (int it = 0; it < NT; ++it) {
        float4 v = ring[it % PF];
        if (it + PF < NT)
            ring[it % PF] = ((it + PF) < NFULL || lane < TAIL) ? __ldcs(Sv + (it + PF) * 32 + lane) : z4;
        unsigned m0 = __ballot_sync(0xffffffffu, v.x != 0.f);
        unsigned m1 = __ballot_sync(0xffffffffu, v.y != 0.f);
        unsigned m2 = __ballot_sync(0xffffffffu, v.z != 0.f);
        unsigned m3 = __ballot_sync(0xffffffffu, v.w != 0.f);
        int t0 = __popc(m0), t1 = __popc(m1), t2 = __popc(m2), t3 = __popc(m3);
        int p0 = cnt + __popc(m0 & lt);
        int p1 = cnt + t0 + __popc(m1 & lt);
        int p2 = cnt + t0 + t1 + __popc(m2 & lt);
        int p3 = cnt + t0 + t1 + t2 + __popc(m3 & lt);
        int base = (it * 32 + lane) * 4;
        if (v.x != 0.f) idxb[p0] = (ushort)(base);
        if (v.y != 0.f) idxb[p1] = (ushort)(base + 1);
        if (v.z != 0.f) idxb[p2] = (ushort)(base + 2);
        if (v.w != 0.f) idxb[p3] = (ushort)(base + 3);
        cnt += t0 + t1 + t2 + t3;
    }
    int cpad = (cnt + 7) & ~7;
    if (lane < cpad - cnt) idxb[cnt + lane] = (ushort)npad;  // dummy -> zeroed table row
    return cpad >> 3;
}

// L2-resident fp16 table gather: per nonzero a lane-coalesced 40B row read (2 sectors).
__device__ __forceinline__ float gather_h(const uint4* __restrict__ ib, int nk,
                                          const __half* __restrict__ tab, int jj)
{
    float a0 = 0.f, a1 = 0.f;
#pragma unroll 2
    for (int k = 0; k < nk; ++k) {
        uint4 w = ib[k];
        a0 += __half2float(__ldg(tab + ((w.x & 0xffffu) * TSTR + jj)));
        a1 += __half2float(__ldg(tab + ((w.x >> 16)     * TSTR + jj)));
        a0 += __half2float(__ldg(tab + ((w.y & 0xffffu) * TSTR + jj)));
        a1 += __half2float(__ldg(tab + ((w.y >> 16)     * TSTR + jj)));
        a0 += __half2float(__ldg(tab + ((w.z & 0xffffu) * TSTR + jj)));
        a1 += __half2float(__ldg(tab + ((w.z >> 16)     * TSTR + jj)));
        a0 += __half2float(__ldg(tab + ((w.w & 0xffffu) * TSTR + jj)));
        a1 += __half2float(__ldg(tab + ((w.w >> 16)     * TSTR + jj)));
    }
    return a0 + a1;
}

#define K2_THREADS 256
#define K2_WARPS   8
#define K2_BLOCKS  (148 * 4)   // exactly one wave, all co-resident (spin-safe)

__global__ void __launch_bounds__(K2_THREADS, 4)
spike_kernel(const float* __restrict__ Se, const float* __restrict__ Si,
             const float* __restrict__ Craw_e, const float* __restrict__ Craw_i,
             const float* __restrict__ Wsyn, const float* __restrict__ Tausyn,
             const float* __restrict__ Dsyn, const float* __restrict__ Wsub,
             const float* __restrict__ Vo, const float* __restrict__ Theta,
             float* __restrict__ out)
{
    __shared__ __align__(16) ushort idx_s[K2_WARPS][272];

    // --- prep slice (each thread handles at most one prep index) ---
    int gtid = blockIdx.x * K2_THREADS + threadIdx.x;
    if (gtid < N_PREP)
        do_prep(gtid, Craw_e, Craw_i, Wsyn, Tausyn, Dsyn, Wsub, Vo, Theta, out);
    __threadfence();
    __syncthreads();
    if (threadIdx.x == 0) atomicAdd(&g_done, 1);

    int warp = threadIdx.x >> 5;
    int lane = threadIdx.x & 31;
    unsigned lt = (1u << lane) - 1u;
    int jj = (lane < SUB_NO) ? lane : 0;
    ushort* idxb = idx_s[warp];

    int gwarp = blockIdx.x * K2_WARPS + warp;
    bool ready = false;

    for (int row = gwarp; row < T_DATA; row += K2_BLOCKS * K2_WARPS) {
        // ---- E: scan (overlaps prep on first trip), then gather ----
        int enk = row_scan<15, 20, 5>((const float4*)(Se + (size_t)row * E_NO), E_NO,
                                      idxb, lane, lt);
        __syncwarp();
        if (!ready) {   // wait once until all blocks' prep slices are visible
            while (*(volatile int*)&g_done < K2_BLOCKS) __nanosleep(200);
            __threadfence();
            ready = true;
        }
        float ae = gather_h((const uint4*)idxb, enk, g_TEh, jj);
        __syncwarp();

        // ---- I: scan + gather ----
        int ink = row_scan<3, 29, 3>((const float4*)(Si + (size_t)row * I_NO), I_NO,
                                     idxb, lane, lt);
        __syncwarp();
        float ai = gather_h((const uint4*)idxb, ink, g_TIh, jj);
        __syncwarp();

        if (lane < SUB_NO) {
            g_synZe[(PAD + row) * SUB_NO + lane] = ae;
            g_synZi[(PAD + row) * SUB_NO + lane] = ai;
        }
    }
}

// ---------------- K2: fused IIR + tree (smem staged) ----------------
#define CHU  32
#define NCH  (T_DATA / CHU)    // 625
#define NIT  (PAD + CHU)       // 80, compile-time
#define RD   16
#define PAIRS_PER_BLK 8
#define IT_THREADS (PAIRS_PER_BLK * 64)  // 512

__device__ __forceinline__ float fast_tanh(float x)
{
    x = fminf(fmaxf(x, -15.f), 15.f);
    float e = __expf(2.f * x);
    return __fdividef(e - 1.f, e + 1.f);
}

__global__ void __launch_bounds__(IT_THREADS)
iirtree_kernel(float* __restrict__ out)
{
    // reset the prep barrier for the next graph replay (this kernel always runs last)
    if (blockIdx.x == 0 && threadIdx.x == 0) g_done = 0;

    __shared__ float syn2[PAIRS_PER_BLK][2][CHU][21];
    int w    = threadIdx.x >> 6;
    int type = (threadIdx.x >> 5) & 1;
    int lane = threadIdx.x & 31;
    int chunk = blockIdx.x * PAIRS_PER_BLK + w;

    if (chunk < NCH && lane < SUB_NO) {
        int s = lane;
        const float* __restrict__ x = (type ? g_synZi : g_synZe) + chunk * CHU * SUB_NO + s;
        float r  = g_par[(type ? P_RI  : P_RE ) + s];
        float B  = g_par[(type ? P_BI  : P_BE ) + s];
        float BD = g_par[(type ? P_BDI : P_BDE) + s];
        float C1 = g_par[(type ? P_C1I : P_C1E) + s];

        float ring[RD];
#pragma unroll
        for (int p = 0; p < RD; ++p) ring[p] = x[p * SUB_NO];

        float s1 = 0.f, s2 = 0.f, xp = 0.f;
#pragma unroll
        for (int k = 0; k < NIT; ++k) {
            float xv = ring[k % RD];
            if (k + RD < NIT) ring[k % RD] = x[(k + RD) * SUB_NO];
            float ns2 = r * (s1 + s2);
            s1 = fmaf(r, s1, xv);
            s2 = ns2;
            if (k >= PAD)
                syn2[w][type][k - PAD][s] = B * s2 - BD * s1 + BD * xv + C1 * xp;
            xp = xv;
        }
    }
    __syncthreads();

    if (chunk < NCH && type == 0) {
        int t = chunk * CHU + lane;
        float syn[SUB_NO];
#pragma unroll
        for (int s = 0; s < SUB_NO; ++s)
            syn[s] = syn2[w][0][lane][s] + syn2[w][1][lane][s];

        float gain[SUB_NO], th[SUB_NO];
#pragma unroll
        for (int j = 0; j < SUB_NO; ++j) { gain[j] = g_par[P_GAIN + j]; th[j] = g_par[P_THETA + j]; }

        float sub[SUB_NO];
#pragma unroll
        for (int i = SUB_NO - 1; i >= 0; --i) {
            float v = syn[i] + th[i];
            if (2 * i + 1 < SUB_NO) v = fmaf(gain[2 * i + 1], sub[2 * i + 1], v);
            if (2 * i + 2 < SUB_NO) v = fmaf(gain[2 * i + 2], sub[2 * i + 2], v);
            sub[i] = fast_tanh(v);
        }
        out[t] = fmaf(sub[0], gain[0], g_par[P_VO]);
    }
}

// ---------------- launch ----------------
extern "C" void kernel_launch(void* const* d_in, const int* in_sizes, int n_in,
                              void* d_out, int out_size)
{
    const float* Se     = (const float*)d_in[0];
    const float* Si     = (const float*)d_in[1];
    const float* Wsyn   = (const float*)d_in[3];
    const float* Tausyn = (const float*)d_in[4];
    const float* Dsyn   = (const float*)d_in[5];
    const float* Wsub   = (const float*)d_in[6];
    const float* Vo     = (const float*)d_in[7];
    const float* Theta  = (const float*)d_in[8];
    const float* Ce     = (const float*)d_in[9];
    const float* Ci     = (const float*)d_in[10];
    float* out = (float*)d_out;

    spike_kernel<<<K2_BLOCKS, K2_THREADS>>>(Se, Si, Ce, Ci, Wsyn, Tausyn, Dsyn,
                                            Wsub, Vo, Theta, out);

    iirtree_kernel<<<(NCH + PAIRS_PER_BLK - 1) / PAIRS_PER_BLK, IT_THREADS>>>(out);
}